// round 4
// baseline (speedup 1.0000x reference)
#include <cuda_runtime.h>
#include <cstdint>

// ---------------------------------------------------------------------------
// fused: out = relu(x@Wc^T + mean_k(x[nh])@Wn^T + mean_k(e)@We^T)
// mma.sync m16n8k8 tf32 (sm_80+ path; tcgen05 unavailable: harness targets sm_103)
// M=128 rows/tile, N=128, K=320 = [x(128)|xnj(128)|xej(64)]
// NOTE: ij is int32 (JAX x64 disabled downcasts the requested int64).
// ---------------------------------------------------------------------------

#define FULLMASK 0xFFFFFFFFu

static constexpr int NR     = 100000;
static constexpr int TM     = 128;                  // rows per tile
static constexpr int NTILES = (NR + TM - 1) / TM;   // 782
static constexpr int AS     = 324;                  // A smem stride (floats), ≡4 mod 32
static constexpr int WS     = 68;                   // W chunk stride (floats), ≡4 mod 32
static constexpr int KCH    = 64;                   // K per W chunk
static constexpr int NCH    = 5;                    // 5 * 64 = 320
static constexpr unsigned A_ELEMS  = TM * AS;       // 41472
static constexpr unsigned W_ELEMS  = 128 * WS;      // 8704
static constexpr unsigned SMEM_DYN = (A_ELEMS + W_ELEMS) * 4;  // 200704 B

static __device__ __forceinline__ uint32_t f2tf(float f) {
    uint32_t r;
    asm("cvt.rna.tf32.f32 %0, %1;" : "=r"(r) : "f"(f));
    return r;
}

static __device__ __forceinline__ void mma8(float* c, const uint32_t* a,
                                            uint32_t b0, uint32_t b1) {
    asm volatile(
        "mma.sync.aligned.m16n8k8.row.col.f32.tf32.tf32.f32 "
        "{%0,%1,%2,%3}, {%4,%5,%6,%7}, {%8,%9}, {%0,%1,%2,%3};"
        : "+f"(c[0]), "+f"(c[1]), "+f"(c[2]), "+f"(c[3])
        : "r"(a[0]), "r"(a[1]), "r"(a[2]), "r"(a[3]), "r"(b0), "r"(b1));
}

// Load one 128x64 K-chunk of the concatenated weight [Wc|Wn|We] into SMEM (tf32)
static __device__ __forceinline__ void load_wchunk(
    uint32_t* __restrict__ Wsm, int c,
    const float* __restrict__ Wc, const float* __restrict__ Wn,
    const float* __restrict__ We, int tid)
{
    const float* src; int koff; int sk;
    if (c < 2)      { src = Wc; koff = c * 64;       sk = 128; }
    else if (c < 4) { src = Wn; koff = (c - 2) * 64; sk = 128; }
    else            { src = We; koff = 0;            sk = 64;  }
    #pragma unroll
    for (int i = 0; i < 8; i++) {
        const int idx  = tid + i * 256;   // 0..2047 float4s
        const int nrow = idx >> 4;        // output feature (0..127)
        const int k4   = idx & 15;        // float4 within 64-float chunk
        const float4 v = *(const float4*)(src + nrow * sk + koff + k4 * 4);
        uint32_t* d = Wsm + nrow * WS + k4 * 4;
        d[0] = f2tf(v.x); d[1] = f2tf(v.y); d[2] = f2tf(v.z); d[3] = f2tf(v.w);
    }
}

__global__ void __launch_bounds__(256, 1)
conv_block_fused(const float* __restrict__ x, const float* __restrict__ e,
                 const int* __restrict__ ij,
                 const float* __restrict__ Wc, const float* __restrict__ Wn,
                 const float* __restrict__ We, float* __restrict__ out)
{
    extern __shared__ uint32_t smem[];
    uint32_t* As = smem;             // A tile, tf32 bits, [128][AS]
    uint32_t* Wsm = smem + A_ELEMS;  // W chunk, tf32 bits, [128][WS]

    const int tid  = threadIdx.x;
    const int wid  = tid >> 5;
    const int lane = tid & 31;
    const int gid  = lane >> 2;      // 0..7
    const int tq   = lane & 3;       // 0..3
    const long long row0 = (long long)blockIdx.x * TM;

    // ---------------- build A tile: warp per row, lane per column ----------
    {
        const float inv = 1.0f / 16.0f;
        #pragma unroll 1
        for (int rr = 0; rr < 16; rr++) {
            const int r = wid * 16 + rr;
            const long long rg = row0 + r;
            const bool valid = (rg < NR);

            // ij: (N, 16, 2) int32; neighbor index = component 0
            int nhi = 0;
            if (valid && lane < 16) nhi = ij[rg * 32 + lane * 2];
            int rk[16];
            #pragma unroll
            for (int k = 0; k < 16; k++) rk[k] = __shfl_sync(FULLMASK, nhi, k);

            float4 xv = make_float4(0.f, 0.f, 0.f, 0.f);
            float4 ac = make_float4(0.f, 0.f, 0.f, 0.f);
            if (valid) {
                xv = *(const float4*)(x + rg * 128 + lane * 4);
                #pragma unroll
                for (int k = 0; k < 16; k++) {
                    const float4 t = *(const float4*)(x + (long long)rk[k] * 128 + lane * 4);
                    ac.x += t.x; ac.y += t.y; ac.z += t.z; ac.w += t.w;
                }
            }
            ac.x *= inv; ac.y *= inv; ac.z *= inv; ac.w *= inv;

            uint32_t* a0 = As + r * AS + lane * 4;
            a0[0] = f2tf(xv.x); a0[1] = f2tf(xv.y); a0[2] = f2tf(xv.z); a0[3] = f2tf(xv.w);
            uint32_t* a1 = As + r * AS + 128 + lane * 4;
            a1[0] = f2tf(ac.x); a1[1] = f2tf(ac.y); a1[2] = f2tf(ac.z); a1[3] = f2tf(ac.w);

            float2 ea = make_float2(0.f, 0.f);
            if (valid) {
                const float2* ep = (const float2*)(e + rg * 1024 + lane * 2);
                #pragma unroll
                for (int k = 0; k < 16; k++) {
                    const float2 t = ep[k * 32];
                    ea.x += t.x; ea.y += t.y;
                }
            }
            ea.x *= inv; ea.y *= inv;
            uint32_t* a2 = As + r * AS + 256 + lane * 2;
            a2[0] = f2tf(ea.x); a2[1] = f2tf(ea.y);
        }
    }

    // ---------------- GEMM: mma.sync tf32, warp tile 32(M) x 64(N) --------
    const int m0 = (wid & 3) * 32;
    const int n0 = (wid >> 2) * 64;

    float acc[2][8][4];
    #pragma unroll
    for (int mt = 0; mt < 2; mt++)
        #pragma unroll
        for (int j = 0; j < 8; j++)
            #pragma unroll
            for (int q = 0; q < 4; q++) acc[mt][j][q] = 0.f;

    load_wchunk(Wsm, 0, Wc, Wn, We, tid);
    __syncthreads();   // A tile + W chunk 0 ready

    #pragma unroll 1
    for (int c = 0; c < NCH; c++) {
        const int kbase = c * KCH;
        #pragma unroll 2
        for (int ks = 0; ks < 8; ks++) {
            const int kk = ks * 8;
            // A fragments (2 m16 tiles)
            uint32_t afr[2][4];
            #pragma unroll
            for (int mt = 0; mt < 2; mt++) {
                const uint32_t* Ap = As + (m0 + mt * 16 + gid) * AS + kbase + kk + tq;
                afr[mt][0] = Ap[0];
                afr[mt][1] = Ap[8 * AS];
                afr[mt][2] = Ap[4];
                afr[mt][3] = Ap[8 * AS + 4];
            }
            // B fragments (8 n8 tiles) + MMA
            const uint32_t* Bp = Wsm + (n0 + gid) * WS + kk + tq;
            #pragma unroll
            for (int j = 0; j < 8; j++) {
                const uint32_t b0 = Bp[j * 8 * WS];
                const uint32_t b1 = Bp[j * 8 * WS + 4];
                mma8(acc[0][j], afr[0], b0, b1);
                mma8(acc[1][j], afr[1], b0, b1);
            }
        }
        if (c < NCH - 1) {
            __syncthreads();                 // done reading this W chunk
            load_wchunk(Wsm, c + 1, Wc, Wn, We, tid);
            __syncthreads();                 // next chunk ready
        }
    }

    // ---------------- epilogue: relu + store ------------------------------
    #pragma unroll
    for (int mt = 0; mt < 2; mt++) {
        const int rl0 = m0 + mt * 16 + gid;
        const long long rg0 = row0 + rl0;
        const long long rg1 = rg0 + 8;
        #pragma unroll
        for (int j = 0; j < 8; j++) {
            const int col = n0 + j * 8 + tq * 2;
            if (rg0 < NR) {
                float2 v;
                v.x = fmaxf(acc[mt][j][0], 0.f);
                v.y = fmaxf(acc[mt][j][1], 0.f);
                *(float2*)(out + rg0 * 128 + col) = v;
            }
            if (rg1 < NR) {
                float2 v;
                v.x = fmaxf(acc[mt][j][2], 0.f);
                v.y = fmaxf(acc[mt][j][3], 0.f);
                *(float2*)(out + rg1 * 128 + col) = v;
            }
        }
    }
}

extern "C" void kernel_launch(void* const* d_in, const int* in_sizes, int n_in,
                              void* d_out, int out_size)
{
    (void)in_sizes; (void)n_in; (void)out_size;
    const float* x  = (const float*)d_in[0];
    const float* e  = (const float*)d_in[1];
    const int*   ij = (const int*)d_in[2];
    const float* Wc = (const float*)d_in[3];
    const float* Wn = (const float*)d_in[4];
    const float* We = (const float*)d_in[5];

    cudaFuncSetAttribute(conv_block_fused,
                         cudaFuncAttributeMaxDynamicSharedMemorySize, SMEM_DYN);
    conv_block_fused<<<NTILES, 256, SMEM_DYN>>>(x, e, ij, Wc, Wn, We, (float*)d_out);
}

// round 5
// speedup vs baseline: 1.1238x; 1.1238x over previous
#include <cuda_runtime.h>
#include <cstdint>

// ---------------------------------------------------------------------------
// fused: out = relu(x@Wc^T + mean_k(x[nh])@Wn^T + mean_k(e)@We^T)
// mma.sync m16n8k8 tf32; M=128 rows/tile, N=128, K=320 = [x|mean x[nh]|mean e]
// 512 threads/CTA (16 warps) to double latency hiding; ij is int32.
// ---------------------------------------------------------------------------

#define FULLMASK 0xFFFFFFFFu

static constexpr int NR     = 100000;
static constexpr int TM     = 128;                  // rows per tile
static constexpr int NTILES = (NR + TM - 1) / TM;   // 782
static constexpr int AS     = 324;                  // A smem stride (floats), ≡4 mod 32
static constexpr int WS     = 68;                   // W chunk stride (floats), ≡4 mod 32
static constexpr int KCH    = 64;                   // K per W chunk
static constexpr int NCH    = 5;                    // 5 * 64 = 320
static constexpr int NTHR   = 512;
static constexpr unsigned A_ELEMS  = TM * AS;       // 41472
static constexpr unsigned W_ELEMS  = 128 * WS;      // 8704
static constexpr unsigned SMEM_DYN = (A_ELEMS + W_ELEMS) * 4;  // 200704 B

static __device__ __forceinline__ uint32_t f2tf(float f) {
    uint32_t r;
    asm("cvt.rna.tf32.f32 %0, %1;" : "=r"(r) : "f"(f));
    return r;
}

static __device__ __forceinline__ void mma8(float* c, const uint32_t* a,
                                            uint32_t b0, uint32_t b1) {
    asm volatile(
        "mma.sync.aligned.m16n8k8.row.col.f32.tf32.tf32.f32 "
        "{%0,%1,%2,%3}, {%4,%5,%6,%7}, {%8,%9}, {%0,%1,%2,%3};"
        : "+f"(c[0]), "+f"(c[1]), "+f"(c[2]), "+f"(c[3])
        : "r"(a[0]), "r"(a[1]), "r"(a[2]), "r"(a[3]), "r"(b0), "r"(b1));
}

// Load one 128x64 K-chunk of the concatenated weight [Wc|Wn|We] into SMEM (tf32)
static __device__ __forceinline__ void load_wchunk(
    uint32_t* __restrict__ Wsm, int c,
    const float* __restrict__ Wc, const float* __restrict__ Wn,
    const float* __restrict__ We, int tid)
{
    const float* src; int koff; int sk;
    if (c < 2)      { src = Wc; koff = c * 64;       sk = 128; }
    else if (c < 4) { src = Wn; koff = (c - 2) * 64; sk = 128; }
    else            { src = We; koff = 0;            sk = 64;  }
    #pragma unroll
    for (int i = 0; i < 4; i++) {
        const int idx  = tid + i * NTHR;  // 0..2047 float4s
        const int nrow = idx >> 4;        // output feature (0..127)
        const int k4   = idx & 15;        // float4 within 64-float chunk
        const float4 v = *(const float4*)(src + nrow * sk + koff + k4 * 4);
        uint32_t* d = Wsm + nrow * WS + k4 * 4;
        d[0] = f2tf(v.x); d[1] = f2tf(v.y); d[2] = f2tf(v.z); d[3] = f2tf(v.w);
    }
}

__global__ void __launch_bounds__(NTHR, 1)
conv_block_fused(const float* __restrict__ x, const float* __restrict__ e,
                 const int* __restrict__ ij,
                 const float* __restrict__ Wc, const float* __restrict__ Wn,
                 const float* __restrict__ We, float* __restrict__ out)
{
    extern __shared__ uint32_t smem[];
    uint32_t* As = smem;             // A tile, tf32 bits, [128][AS]
    uint32_t* Wsm = smem + A_ELEMS;  // W chunk, tf32 bits, [128][WS]

    const int tid  = threadIdx.x;
    const int wid  = tid >> 5;       // 0..15
    const int lane = tid & 31;
    const int gid  = lane >> 2;      // 0..7
    const int tq   = lane & 3;       // 0..3
    const int row0 = blockIdx.x * TM;

    // ---------------- build A tile: warp per row, lane per column ----------
    {
        const float inv = 1.0f / 16.0f;
        #pragma unroll 1
        for (int rr = 0; rr < 8; rr++) {
            const int r  = wid * 8 + rr;
            const int rg = row0 + r;
            const bool valid = (rg < NR);

            // ij: (N, 16, 2) int32; neighbor index = component 0
            int nhi = 0;
            if (valid && lane < 16) nhi = __ldg(ij + rg * 32 + lane * 2);
            int rk[16];
            #pragma unroll
            for (int k = 0; k < 16; k++) rk[k] = __shfl_sync(FULLMASK, nhi, k);

            float4 xv = make_float4(0.f, 0.f, 0.f, 0.f);
            float4 ac = make_float4(0.f, 0.f, 0.f, 0.f);
            if (valid) {
                xv = *(const float4*)(x + rg * 128 + lane * 4);
                #pragma unroll
                for (int k = 0; k < 16; k++) {
                    const float4 t = *(const float4*)(x + rk[k] * 128 + lane * 4);
                    ac.x += t.x; ac.y += t.y; ac.z += t.z; ac.w += t.w;
                }
            }
            ac.x *= inv; ac.y *= inv; ac.z *= inv; ac.w *= inv;

            uint32_t* a0 = As + r * AS + lane * 4;
            a0[0] = f2tf(xv.x); a0[1] = f2tf(xv.y); a0[2] = f2tf(xv.z); a0[3] = f2tf(xv.w);
            uint32_t* a1 = As + r * AS + 128 + lane * 4;
            a1[0] = f2tf(ac.x); a1[1] = f2tf(ac.y); a1[2] = f2tf(ac.z); a1[3] = f2tf(ac.w);

            float2 ea = make_float2(0.f, 0.f);
            if (valid) {
                const float2* ep = (const float2*)(e + rg * 1024 + lane * 2);
                #pragma unroll
                for (int k = 0; k < 16; k++) {
                    const float2 t = ep[k * 32];
                    ea.x += t.x; ea.y += t.y;
                }
            }
            ea.x *= inv; ea.y *= inv;
            uint32_t* a2 = As + r * AS + 256 + lane * 2;
            a2[0] = f2tf(ea.x); a2[1] = f2tf(ea.y);
        }
    }

    // ---------------- GEMM: mma.sync tf32, warp tile 32(M) x 32(N) --------
    const int m0 = (wid & 3) * 32;
    const int n0 = (wid >> 2) * 32;

    float acc[2][4][4];
    #pragma unroll
    for (int mt = 0; mt < 2; mt++)
        #pragma unroll
        for (int j = 0; j < 4; j++)
            #pragma unroll
            for (int q = 0; q < 4; q++) acc[mt][j][q] = 0.f;

    load_wchunk(Wsm, 0, Wc, Wn, We, tid);
    __syncthreads();   // A tile + W chunk 0 ready

    #pragma unroll 1
    for (int c = 0; c < NCH; c++) {
        const int kbase = c * KCH;
        #pragma unroll 2
        for (int ks = 0; ks < 8; ks++) {
            const int kk = ks * 8;
            // A fragments (2 m16 tiles)
            uint32_t afr[2][4];
            #pragma unroll
            for (int mt = 0; mt < 2; mt++) {
                const uint32_t* Ap = As + (m0 + mt * 16 + gid) * AS + kbase + kk + tq;
                afr[mt][0] = Ap[0];
                afr[mt][1] = Ap[8 * AS];
                afr[mt][2] = Ap[4];
                afr[mt][3] = Ap[8 * AS + 4];
            }
            // B fragments (4 n8 tiles) + MMA
            const uint32_t* Bp = Wsm + (n0 + gid) * WS + kk + tq;
            #pragma unroll
            for (int j = 0; j < 4; j++) {
                const uint32_t b0 = Bp[j * 8 * WS];
                const uint32_t b1 = Bp[j * 8 * WS + 4];
                mma8(acc[0][j], afr[0], b0, b1);
                mma8(acc[1][j], afr[1], b0, b1);
            }
        }
        if (c < NCH - 1) {
            __syncthreads();                 // done reading this W chunk
            load_wchunk(Wsm, c + 1, Wc, Wn, We, tid);
            __syncthreads();                 // next chunk ready
        }
    }

    // ---------------- epilogue: relu + store ------------------------------
    #pragma unroll
    for (int mt = 0; mt < 2; mt++) {
        const int rg0 = row0 + m0 + mt * 16 + gid;
        const int rg1 = rg0 + 8;
        #pragma unroll
        for (int j = 0; j < 4; j++) {
            const int col = n0 + j * 8 + tq * 2;
            if (rg0 < NR) {
                float2 v;
                v.x = fmaxf(acc[mt][j][0], 0.f);
                v.y = fmaxf(acc[mt][j][1], 0.f);
                *(float2*)(out + rg0 * 128 + col) = v;
            }
            if (rg1 < NR) {
                float2 v;
                v.x = fmaxf(acc[mt][j][2], 0.f);
                v.y = fmaxf(acc[mt][j][3], 0.f);
                *(float2*)(out + rg1 * 128 + col) = v;
            }
        }
    }
}

extern "C" void kernel_launch(void* const* d_in, const int* in_sizes, int n_in,
                              void* d_out, int out_size)
{
    (void)in_sizes; (void)n_in; (void)out_size;
    const float* x  = (const float*)d_in[0];
    const float* e  = (const float*)d_in[1];
    const int*   ij = (const int*)d_in[2];
    const float* Wc = (const float*)d_in[3];
    const float* Wn = (const float*)d_in[4];
    const float* We = (const float*)d_in[5];

    cudaFuncSetAttribute(conv_block_fused,
                         cudaFuncAttributeMaxDynamicSharedMemorySize, SMEM_DYN);
    conv_block_fused<<<NTILES, NTHR, SMEM_DYN>>>(x, e, ij, Wc, Wn, We, (float*)d_out);
}

// round 6
// speedup vs baseline: 1.1647x; 1.0364x over previous
#include <cuda_runtime.h>
#include <cstdint>

// ---------------------------------------------------------------------------
// fused: out = relu(x@Wc^T + mean_k(x[nh])@Wn^T + mean_k(e)@We^T)
// mma.sync m16n8k8 tf32; M=128 rows/tile, N=128, K=320 = [x|mean x[nh]|mean e]
// 1024 threads/CTA (32 warps) -> 50% occupancy for gather latency hiding.
// ij is int32.
// ---------------------------------------------------------------------------

#define FULLMASK 0xFFFFFFFFu

static constexpr int NR     = 100000;
static constexpr int TM     = 128;                  // rows per tile
static constexpr int NTILES = (NR + TM - 1) / TM;   // 782
static constexpr int AS     = 324;                  // A smem stride (floats), ≡4 mod 32
static constexpr int WS     = 68;                   // W chunk stride (floats), ≡4 mod 32
static constexpr int KCH    = 64;                   // K per W chunk
static constexpr int NCH    = 5;                    // 5 * 64 = 320
static constexpr int NTHR   = 1024;
static constexpr unsigned A_ELEMS  = TM * AS;       // 41472
static constexpr unsigned W_ELEMS  = 128 * WS;      // 8704
static constexpr unsigned SMEM_DYN = (A_ELEMS + W_ELEMS) * 4;  // 200704 B

static __device__ __forceinline__ uint32_t f2tf(float f) {
    uint32_t r;
    asm("cvt.rna.tf32.f32 %0, %1;" : "=r"(r) : "f"(f));
    return r;
}

static __device__ __forceinline__ void mma8(float* c, const uint32_t* a,
                                            uint32_t b0, uint32_t b1) {
    asm volatile(
        "mma.sync.aligned.m16n8k8.row.col.f32.tf32.tf32.f32 "
        "{%0,%1,%2,%3}, {%4,%5,%6,%7}, {%8,%9}, {%0,%1,%2,%3};"
        : "+f"(c[0]), "+f"(c[1]), "+f"(c[2]), "+f"(c[3])
        : "r"(a[0]), "r"(a[1]), "r"(a[2]), "r"(a[3]), "r"(b0), "r"(b1));
}

// Load one 128x64 K-chunk of the concatenated weight [Wc|Wn|We] into SMEM (tf32)
static __device__ __forceinline__ void load_wchunk(
    uint32_t* __restrict__ Wsm, int c,
    const float* __restrict__ Wc, const float* __restrict__ Wn,
    const float* __restrict__ We, int tid)
{
    const float* src; int koff; int sk;
    if (c < 2)      { src = Wc; koff = c * 64;       sk = 128; }
    else if (c < 4) { src = Wn; koff = (c - 2) * 64; sk = 128; }
    else            { src = We; koff = 0;            sk = 64;  }
    #pragma unroll
    for (int i = 0; i < 2; i++) {
        const int idx  = tid + i * NTHR;  // 0..2047 float4s
        const int nrow = idx >> 4;        // output feature (0..127)
        const int k4   = idx & 15;        // float4 within 64-float chunk
        const float4 v = *(const float4*)(src + nrow * sk + koff + k4 * 4);
        uint32_t* d = Wsm + nrow * WS + k4 * 4;
        d[0] = f2tf(v.x); d[1] = f2tf(v.y); d[2] = f2tf(v.z); d[3] = f2tf(v.w);
    }
}

__global__ void __launch_bounds__(NTHR, 1)
conv_block_fused(const float* __restrict__ x, const float* __restrict__ e,
                 const int* __restrict__ ij,
                 const float* __restrict__ Wc, const float* __restrict__ Wn,
                 const float* __restrict__ We, float* __restrict__ out)
{
    extern __shared__ uint32_t smem[];
    uint32_t* As = smem;             // A tile, tf32 bits, [128][AS]
    uint32_t* Wsm = smem + A_ELEMS;  // W chunk, tf32 bits, [128][WS]

    const int tid  = threadIdx.x;
    const int wid  = tid >> 5;       // 0..31
    const int lane = tid & 31;
    const int gid  = lane >> 2;      // 0..7
    const int tq   = lane & 3;       // 0..3
    const int row0 = blockIdx.x * TM;

    // ---------------- build A tile: warp per row, lane per column ----------
    {
        const float inv = 1.0f / 16.0f;
        #pragma unroll 1
        for (int rr = 0; rr < 4; rr++) {
            const int r  = wid * 4 + rr;
            const int rg = row0 + r;
            const bool valid = (rg < NR);

            // ij: (N, 16, 2) int32; neighbor index = component 0
            int nhi = 0;
            if (valid && lane < 16) nhi = __ldg(ij + rg * 32 + lane * 2);
            int rk[16];
            #pragma unroll
            for (int k = 0; k < 16; k++) rk[k] = __shfl_sync(FULLMASK, nhi, k);

            float4 xv = make_float4(0.f, 0.f, 0.f, 0.f);
            float4 ac = make_float4(0.f, 0.f, 0.f, 0.f);
            if (valid) {
                xv = *(const float4*)(x + rg * 128 + lane * 4);
                #pragma unroll
                for (int k = 0; k < 16; k++) {
                    const float4 t = *(const float4*)(x + rk[k] * 128 + lane * 4);
                    ac.x += t.x; ac.y += t.y; ac.z += t.z; ac.w += t.w;
                }
            }
            ac.x *= inv; ac.y *= inv; ac.z *= inv; ac.w *= inv;

            uint32_t* a0 = As + r * AS + lane * 4;
            a0[0] = f2tf(xv.x); a0[1] = f2tf(xv.y); a0[2] = f2tf(xv.z); a0[3] = f2tf(xv.w);
            uint32_t* a1 = As + r * AS + 128 + lane * 4;
            a1[0] = f2tf(ac.x); a1[1] = f2tf(ac.y); a1[2] = f2tf(ac.z); a1[3] = f2tf(ac.w);

            float2 ea = make_float2(0.f, 0.f);
            if (valid) {
                const float2* ep = (const float2*)(e + rg * 1024 + lane * 2);
                #pragma unroll
                for (int k = 0; k < 16; k++) {
                    const float2 t = ep[k * 32];
                    ea.x += t.x; ea.y += t.y;
                }
            }
            ea.x *= inv; ea.y *= inv;
            uint32_t* a2 = As + r * AS + 256 + lane * 2;
            a2[0] = f2tf(ea.x); a2[1] = f2tf(ea.y);
        }
    }

    // ---------------- GEMM: mma.sync tf32, warp tile 16(M) x 32(N) --------
    const int m0 = (wid & 7) * 16;
    const int n0 = (wid >> 3) * 32;

    float acc[4][4];
    #pragma unroll
    for (int j = 0; j < 4; j++)
        #pragma unroll
        for (int q = 0; q < 4; q++) acc[j][q] = 0.f;

    load_wchunk(Wsm, 0, Wc, Wn, We, tid);
    __syncthreads();   // A tile + W chunk 0 ready

    #pragma unroll 1
    for (int c = 0; c < NCH; c++) {
        const int kbase = c * KCH;
        #pragma unroll 2
        for (int ks = 0; ks < 8; ks++) {
            const int kk = ks * 8;
            // A fragment (1 m16 tile)
            uint32_t afr[4];
            const uint32_t* Ap = As + (m0 + gid) * AS + kbase + kk + tq;
            afr[0] = Ap[0];
            afr[1] = Ap[8 * AS];
            afr[2] = Ap[4];
            afr[3] = Ap[8 * AS + 4];
            // B fragments (4 n8 tiles) + MMA
            const uint32_t* Bp = Wsm + (n0 + gid) * WS + kk + tq;
            #pragma unroll
            for (int j = 0; j < 4; j++) {
                const uint32_t b0 = Bp[j * 8 * WS];
                const uint32_t b1 = Bp[j * 8 * WS + 4];
                mma8(acc[j], afr, b0, b1);
            }
        }
        if (c < NCH - 1) {
            __syncthreads();                 // done reading this W chunk
            load_wchunk(Wsm, c + 1, Wc, Wn, We, tid);
            __syncthreads();                 // next chunk ready
        }
    }

    // ---------------- epilogue: relu + store ------------------------------
    {
        const int rg0 = row0 + m0 + gid;
        const int rg1 = rg0 + 8;
        #pragma unroll
        for (int j = 0; j < 4; j++) {
            const int col = n0 + j * 8 + tq * 2;
            if (rg0 < NR) {
                float2 v;
                v.x = fmaxf(acc[j][0], 0.f);
                v.y = fmaxf(acc[j][1], 0.f);
                *(float2*)(out + rg0 * 128 + col) = v;
            }
            if (rg1 < NR) {
                float2 v;
                v.x = fmaxf(acc[j][2], 0.f);
                v.y = fmaxf(acc[j][3], 0.f);
                *(float2*)(out + rg1 * 128 + col) = v;
            }
        }
    }
}

extern "C" void kernel_launch(void* const* d_in, const int* in_sizes, int n_in,
                              void* d_out, int out_size)
{
    (void)in_sizes; (void)n_in; (void)out_size;
    const float* x  = (const float*)d_in[0];
    const float* e  = (const float*)d_in[1];
    const int*   ij = (const int*)d_in[2];
    const float* Wc = (const float*)d_in[3];
    const float* Wn = (const float*)d_in[4];
    const float* We = (const float*)d_in[5];

    cudaFuncSetAttribute(conv_block_fused,
                         cudaFuncAttributeMaxDynamicSharedMemorySize, SMEM_DYN);
    conv_block_fused<<<NTILES, NTHR, SMEM_DYN>>>(x, e, ij, Wc, Wn, We, (float*)d_out);
}

// round 7
// speedup vs baseline: 1.3386x; 1.1492x over previous
#include <cuda_runtime.h>
#include <cstdint>

// ---------------------------------------------------------------------------
// fused: out = relu(x@Wc^T + mean_k(x[nh])@Wn^T + mean_k(e)@We^T)
// mma.sync m16n8k8 tf32; M=128 rows/tile, N=128, K=320 = [x|mean x[nh]|mean e]
// 1024 threads/CTA (32 warps). ij is int32.
// R7: streaming cache hints — e/ij loads evict-first (__ldcs), out stores
//     __stcs — so the 410MB e stream stops evicting the L2-resident x table,
//     dropping gather latency from DRAM-tier to L2-tier.
// ---------------------------------------------------------------------------

#define FULLMASK 0xFFFFFFFFu

static constexpr int NR     = 100000;
static constexpr int TM     = 128;                  // rows per tile
static constexpr int NTILES = (NR + TM - 1) / TM;   // 782
static constexpr int AS     = 324;                  // A smem stride (floats), ≡4 mod 32
static constexpr int WS     = 68;                   // W chunk stride (floats), ≡4 mod 32
static constexpr int KCH    = 64;                   // K per W chunk
static constexpr int NCH    = 5;                    // 5 * 64 = 320
static constexpr int NTHR   = 1024;
static constexpr unsigned A_ELEMS  = TM * AS;       // 41472
static constexpr unsigned W_ELEMS  = 128 * WS;      // 8704
static constexpr unsigned SMEM_DYN = (A_ELEMS + W_ELEMS) * 4;  // 200704 B

static __device__ __forceinline__ uint32_t f2tf(float f) {
    uint32_t r;
    asm("cvt.rna.tf32.f32 %0, %1;" : "=r"(r) : "f"(f));
    return r;
}

static __device__ __forceinline__ void mma8(float* c, const uint32_t* a,
                                            uint32_t b0, uint32_t b1) {
    asm volatile(
        "mma.sync.aligned.m16n8k8.row.col.f32.tf32.tf32.f32 "
        "{%0,%1,%2,%3}, {%4,%5,%6,%7}, {%8,%9}, {%0,%1,%2,%3};"
        : "+f"(c[0]), "+f"(c[1]), "+f"(c[2]), "+f"(c[3])
        : "r"(a[0]), "r"(a[1]), "r"(a[2]), "r"(a[3]), "r"(b0), "r"(b1));
}

// Load one 128x64 K-chunk of the concatenated weight [Wc|Wn|We] into SMEM (tf32)
static __device__ __forceinline__ void load_wchunk(
    uint32_t* __restrict__ Wsm, int c,
    const float* __restrict__ Wc, const float* __restrict__ Wn,
    const float* __restrict__ We, int tid)
{
    const float* src; int koff; int sk;
    if (c < 2)      { src = Wc; koff = c * 64;       sk = 128; }
    else if (c < 4) { src = Wn; koff = (c - 2) * 64; sk = 128; }
    else            { src = We; koff = 0;            sk = 64;  }
    #pragma unroll
    for (int i = 0; i < 2; i++) {
        const int idx  = tid + i * NTHR;  // 0..2047 float4s
        const int nrow = idx >> 4;        // output feature (0..127)
        const int k4   = idx & 15;        // float4 within 64-float chunk
        const float4 v = *(const float4*)(src + nrow * sk + koff + k4 * 4);
        uint32_t* d = Wsm + nrow * WS + k4 * 4;
        d[0] = f2tf(v.x); d[1] = f2tf(v.y); d[2] = f2tf(v.z); d[3] = f2tf(v.w);
    }
}

__global__ void __launch_bounds__(NTHR, 1)
conv_block_fused(const float* __restrict__ x, const float* __restrict__ e,
                 const int* __restrict__ ij,
                 const float* __restrict__ Wc, const float* __restrict__ Wn,
                 const float* __restrict__ We, float* __restrict__ out)
{
    extern __shared__ uint32_t smem[];
    uint32_t* As = smem;             // A tile, tf32 bits, [128][AS]
    uint32_t* Wsm = smem + A_ELEMS;  // W chunk, tf32 bits, [128][WS]

    const int tid  = threadIdx.x;
    const int wid  = tid >> 5;       // 0..31
    const int lane = tid & 31;
    const int gid  = lane >> 2;      // 0..7
    const int tq   = lane & 3;       // 0..3
    const int row0 = blockIdx.x * TM;

    // ---------------- build A tile: warp per row, lane per column ----------
    {
        const float inv = 1.0f / 16.0f;
        #pragma unroll 1
        for (int rr = 0; rr < 4; rr++) {
            const int r  = wid * 4 + rr;
            const int rg = row0 + r;
            const bool valid = (rg < NR);

            // ij: (N, 16, 2) int32; neighbor index = component 0 (read-once)
            int nhi = 0;
            if (valid && lane < 16) nhi = __ldcs(ij + rg * 32 + lane * 2);
            int rk[16];
            #pragma unroll
            for (int k = 0; k < 16; k++) rk[k] = __shfl_sync(FULLMASK, nhi, k);

            float4 xv = make_float4(0.f, 0.f, 0.f, 0.f);
            float4 ac = make_float4(0.f, 0.f, 0.f, 0.f);
            if (valid) {
                xv = *(const float4*)(x + rg * 128 + lane * 4);
                #pragma unroll
                for (int k = 0; k < 16; k++) {
                    // default caching: keep x L2-resident
                    const float4 t = *(const float4*)(x + rk[k] * 128 + lane * 4);
                    ac.x += t.x; ac.y += t.y; ac.z += t.z; ac.w += t.w;
                }
            }
            ac.x *= inv; ac.y *= inv; ac.z *= inv; ac.w *= inv;

            uint32_t* a0 = As + r * AS + lane * 4;
            a0[0] = f2tf(xv.x); a0[1] = f2tf(xv.y); a0[2] = f2tf(xv.z); a0[3] = f2tf(xv.w);
            uint32_t* a1 = As + r * AS + 128 + lane * 4;
            a1[0] = f2tf(ac.x); a1[1] = f2tf(ac.y); a1[2] = f2tf(ac.z); a1[3] = f2tf(ac.w);

            float2 ea = make_float2(0.f, 0.f);
            if (valid) {
                // e is a 410MB read-once stream: evict-first so it never
                // displaces x from L2
                const float2* ep = (const float2*)(e + rg * 1024 + lane * 2);
                #pragma unroll
                for (int k = 0; k < 16; k++) {
                    const float2 t = __ldcs(ep + k * 32);
                    ea.x += t.x; ea.y += t.y;
                }
            }
            ea.x *= inv; ea.y *= inv;
            uint32_t* a2 = As + r * AS + 256 + lane * 2;
            a2[0] = f2tf(ea.x); a2[1] = f2tf(ea.y);
        }
    }

    // ---------------- GEMM: mma.sync tf32, warp tile 16(M) x 32(N) --------
    const int m0 = (wid & 7) * 16;
    const int n0 = (wid >> 3) * 32;

    float acc[4][4];
    #pragma unroll
    for (int j = 0; j < 4; j++)
        #pragma unroll
        for (int q = 0; q < 4; q++) acc[j][q] = 0.f;

    load_wchunk(Wsm, 0, Wc, Wn, We, tid);
    __syncthreads();   // A tile + W chunk 0 ready

    #pragma unroll 1
    for (int c = 0; c < NCH; c++) {
        const int kbase = c * KCH;
        #pragma unroll 2
        for (int ks = 0; ks < 8; ks++) {
            const int kk = ks * 8;
            // A fragment (1 m16 tile)
            uint32_t afr[4];
            const uint32_t* Ap = As + (m0 + gid) * AS + kbase + kk + tq;
            afr[0] = Ap[0];
            afr[1] = Ap[8 * AS];
            afr[2] = Ap[4];
            afr[3] = Ap[8 * AS + 4];
            // B fragments (4 n8 tiles) + MMA
            const uint32_t* Bp = Wsm + (n0 + gid) * WS + kk + tq;
            #pragma unroll
            for (int j = 0; j < 4; j++) {
                const uint32_t b0 = Bp[j * 8 * WS];
                const uint32_t b1 = Bp[j * 8 * WS + 4];
                mma8(acc[j], afr, b0, b1);
            }
        }
        if (c < NCH - 1) {
            __syncthreads();                 // done reading this W chunk
            load_wchunk(Wsm, c + 1, Wc, Wn, We, tid);
            __syncthreads();                 // next chunk ready
        }
    }

    // ---------------- epilogue: relu + store (write-once: streaming) ------
    {
        const int rg0 = row0 + m0 + gid;
        const int rg1 = rg0 + 8;
        #pragma unroll
        for (int j = 0; j < 4; j++) {
            const int col = n0 + j * 8 + tq * 2;
            if (rg0 < NR) {
                float2 v;
                v.x = fmaxf(acc[j][0], 0.f);
                v.y = fmaxf(acc[j][1], 0.f);
                __stcs((float2*)(out + rg0 * 128 + col), v);
            }
            if (rg1 < NR) {
                float2 v;
                v.x = fmaxf(acc[j][2], 0.f);
                v.y = fmaxf(acc[j][3], 0.f);
                __stcs((float2*)(out + rg1 * 128 + col), v);
            }
        }
    }
}

extern "C" void kernel_launch(void* const* d_in, const int* in_sizes, int n_in,
                              void* d_out, int out_size)
{
    (void)in_sizes; (void)n_in; (void)out_size;
    const float* x  = (const float*)d_in[0];
    const float* e  = (const float*)d_in[1];
    const int*   ij = (const int*)d_in[2];
    const float* Wc = (const float*)d_in[3];
    const float* Wn = (const float*)d_in[4];
    const float* We = (const float*)d_in[5];

    cudaFuncSetAttribute(conv_block_fused,
                         cudaFuncAttributeMaxDynamicSharedMemorySize, SMEM_DYN);
    conv_block_fused<<<NTILES, NTHR, SMEM_DYN>>>(x, e, ij, Wc, Wn, We, (float*)d_out);
}

// round 8
// speedup vs baseline: 1.5228x; 1.1376x over previous
#include <cuda_runtime.h>
#include <cstdint>

// ---------------------------------------------------------------------------
// fused: out = relu(x@Wc^T + mean_k(x[nh])@Wn^T + mean_k(e)@We^T)
// mma.sync m16n8k8 tf32; M=64 rows/tile, N=128, K=320 = [x|mean x[nh]|mean e]
// R8: TM=64 + 99KB SMEM/CTA -> 2 CTAs/SM so one CTA's GEMM overlaps the
//     other's gather phase. 512 thr/CTA, ij int32, streaming hints kept.
// ---------------------------------------------------------------------------

#define FULLMASK 0xFFFFFFFFu

static constexpr int NR     = 100000;
static constexpr int TM     = 64;                   // rows per tile
static constexpr int NTILES = (NR + TM - 1) / TM;   // 1563
static constexpr int AS     = 324;                  // A smem stride (floats), ≡4 mod 32
static constexpr int WS     = 36;                   // W chunk stride (floats), ≡4 mod 32
static constexpr int KCH    = 32;                   // K per W chunk
static constexpr int NCH    = 10;                   // 10 * 32 = 320
static constexpr int NTHR   = 512;
static constexpr unsigned A_ELEMS  = TM * AS;       // 20736
static constexpr unsigned W_ELEMS  = 128 * WS;      // 4608
static constexpr unsigned SMEM_DYN = (A_ELEMS + W_ELEMS) * 4;  // 101376 B

static __device__ __forceinline__ uint32_t f2tf(float f) {
    uint32_t r;
    asm("cvt.rna.tf32.f32 %0, %1;" : "=r"(r) : "f"(f));
    return r;
}

static __device__ __forceinline__ void mma8(float* c, const uint32_t* a,
                                            uint32_t b0, uint32_t b1) {
    asm volatile(
        "mma.sync.aligned.m16n8k8.row.col.f32.tf32.tf32.f32 "
        "{%0,%1,%2,%3}, {%4,%5,%6,%7}, {%8,%9}, {%0,%1,%2,%3};"
        : "+f"(c[0]), "+f"(c[1]), "+f"(c[2]), "+f"(c[3])
        : "r"(a[0]), "r"(a[1]), "r"(a[2]), "r"(a[3]), "r"(b0), "r"(b1));
}

// Load one 128x32 K-chunk of the concatenated weight [Wc|Wn|We] into SMEM (tf32)
static __device__ __forceinline__ void load_wchunk(
    uint32_t* __restrict__ Wsm, int c,
    const float* __restrict__ Wc, const float* __restrict__ Wn,
    const float* __restrict__ We, int tid)
{
    const float* src; int koff; int sk;
    if (c < 4)      { src = Wc; koff = c * 32;       sk = 128; }
    else if (c < 8) { src = Wn; koff = (c - 4) * 32; sk = 128; }
    else            { src = We; koff = (c - 8) * 32; sk = 64;  }
    #pragma unroll
    for (int i = 0; i < 2; i++) {
        const int idx  = tid + i * NTHR;  // 0..1023 float4s
        const int nrow = idx >> 3;        // output feature (0..127)
        const int k4   = idx & 7;         // float4 within 32-float chunk
        const float4 v = *(const float4*)(src + nrow * sk + koff + k4 * 4);
        uint32_t* d = Wsm + nrow * WS + k4 * 4;
        d[0] = f2tf(v.x); d[1] = f2tf(v.y); d[2] = f2tf(v.z); d[3] = f2tf(v.w);
    }
}

__global__ void __launch_bounds__(NTHR, 2)
conv_block_fused(const float* __restrict__ x, const float* __restrict__ e,
                 const int* __restrict__ ij,
                 const float* __restrict__ Wc, const float* __restrict__ Wn,
                 const float* __restrict__ We, float* __restrict__ out)
{
    extern __shared__ uint32_t smem[];
    uint32_t* As = smem;             // A tile, tf32 bits, [64][AS]
    uint32_t* Wsm = smem + A_ELEMS;  // W chunk, tf32 bits, [128][WS]

    const int tid  = threadIdx.x;
    const int wid  = tid >> 5;       // 0..15
    const int lane = tid & 31;
    const int gid  = lane >> 2;      // 0..7
    const int tq   = lane & 3;       // 0..3
    const int row0 = blockIdx.x * TM;

    // ---------------- build A tile: warp per row, lane per column ----------
    {
        const float inv = 1.0f / 16.0f;
        const int r0  = wid * 4;
        const int rgb = row0 + r0;

        // prefetch ij for all 4 rows of this warp (2 streamed LDGs)
        int nh01 = 0, nh23 = 0;
        {
            const int rowsel = lane >> 4;       // 0 or 1
            const int nidx   = lane & 15;
            const int ra = rgb + rowsel;
            const int rb = rgb + 2 + rowsel;
            if (ra < NR) nh01 = __ldcs(ij + ra * 32 + nidx * 2);
            if (rb < NR) nh23 = __ldcs(ij + rb * 32 + nidx * 2);
        }

        #pragma unroll 1
        for (int rr = 0; rr < 4; rr++) {
            const int r  = r0 + rr;
            const int rg = row0 + r;
            const bool valid = (rg < NR);

            const int nsrc = (rr < 2) ? nh01 : nh23;
            int rk[16];
            #pragma unroll
            for (int k = 0; k < 16; k++)
                rk[k] = __shfl_sync(FULLMASK, nsrc, (rr & 1) * 16 + k);

            float4 xv = make_float4(0.f, 0.f, 0.f, 0.f);
            float4 ac = make_float4(0.f, 0.f, 0.f, 0.f);
            if (valid) {
                xv = *(const float4*)(x + rg * 128 + lane * 4);
                #pragma unroll
                for (int k = 0; k < 16; k++) {
                    // default caching: keep x L2-resident
                    const float4 t = *(const float4*)(x + rk[k] * 128 + lane * 4);
                    ac.x += t.x; ac.y += t.y; ac.z += t.z; ac.w += t.w;
                }
            }
            ac.x *= inv; ac.y *= inv; ac.z *= inv; ac.w *= inv;

            uint32_t* a0 = As + r * AS + lane * 4;
            a0[0] = f2tf(xv.x); a0[1] = f2tf(xv.y); a0[2] = f2tf(xv.z); a0[3] = f2tf(xv.w);
            uint32_t* a1 = As + r * AS + 128 + lane * 4;
            a1[0] = f2tf(ac.x); a1[1] = f2tf(ac.y); a1[2] = f2tf(ac.z); a1[3] = f2tf(ac.w);

            float2 ea = make_float2(0.f, 0.f);
            if (valid) {
                // e is a read-once stream: evict-first
                const float2* ep = (const float2*)(e + rg * 1024 + lane * 2);
                #pragma unroll
                for (int k = 0; k < 16; k++) {
                    const float2 t = __ldcs(ep + k * 32);
                    ea.x += t.x; ea.y += t.y;
                }
            }
            ea.x *= inv; ea.y *= inv;
            uint32_t* a2 = As + r * AS + 256 + lane * 2;
            a2[0] = f2tf(ea.x); a2[1] = f2tf(ea.y);
        }
    }

    // ---------------- GEMM: mma.sync tf32, warp tile 16(M) x 32(N) --------
    const int m0 = (wid & 3) * 16;
    const int n0 = (wid >> 2) * 32;

    float acc[4][4];
    #pragma unroll
    for (int j = 0; j < 4; j++)
        #pragma unroll
        for (int q = 0; q < 4; q++) acc[j][q] = 0.f;

    load_wchunk(Wsm, 0, Wc, Wn, We, tid);
    __syncthreads();   // A tile + W chunk 0 ready

    #pragma unroll 1
    for (int c = 0; c < NCH; c++) {
        const int kbase = c * KCH;
        #pragma unroll
        for (int ks = 0; ks < 4; ks++) {
            const int kk = ks * 8;
            // A fragment (1 m16 tile)
            uint32_t afr[4];
            const uint32_t* Ap = As + (m0 + gid) * AS + kbase + kk + tq;
            afr[0] = Ap[0];
            afr[1] = Ap[8 * AS];
            afr[2] = Ap[4];
            afr[3] = Ap[8 * AS + 4];
            // B fragments (4 n8 tiles) + MMA
            const uint32_t* Bp = Wsm + (n0 + gid) * WS + kk + tq;
            #pragma unroll
            for (int j = 0; j < 4; j++) {
                const uint32_t b0 = Bp[j * 8 * WS];
                const uint32_t b1 = Bp[j * 8 * WS + 4];
                mma8(acc[j], afr, b0, b1);
            }
        }
        if (c < NCH - 1) {
            __syncthreads();                 // done reading this W chunk
            load_wchunk(Wsm, c + 1, Wc, Wn, We, tid);
            __syncthreads();                 // next chunk ready
        }
    }

    // ---------------- epilogue: relu + store (write-once: streaming) ------
    {
        const int rg0 = row0 + m0 + gid;
        const int rg1 = rg0 + 8;
        #pragma unroll
        for (int j = 0; j < 4; j++) {
            const int col = n0 + j * 8 + tq * 2;
            if (rg0 < NR) {
                float2 v;
                v.x = fmaxf(acc[j][0], 0.f);
                v.y = fmaxf(acc[j][1], 0.f);
                __stcs((float2*)(out + rg0 * 128 + col), v);
            }
            if (rg1 < NR) {
                float2 v;
                v.x = fmaxf(acc[j][2], 0.f);
                v.y = fmaxf(acc[j][3], 0.f);
                __stcs((float2*)(out + rg1 * 128 + col), v);
            }
        }
    }
}

extern "C" void kernel_launch(void* const* d_in, const int* in_sizes, int n_in,
                              void* d_out, int out_size)
{
    (void)in_sizes; (void)n_in; (void)out_size;
    const float* x  = (const float*)d_in[0];
    const float* e  = (const float*)d_in[1];
    const int*   ij = (const int*)d_in[2];
    const float* Wc = (const float*)d_in[3];
    const float* Wn = (const float*)d_in[4];
    const float* We = (const float*)d_in[5];

    cudaFuncSetAttribute(conv_block_fused,
                         cudaFuncAttributeMaxDynamicSharedMemorySize, SMEM_DYN);
    conv_block_fused<<<NTILES, NTHR, SMEM_DYN>>>(x, e, ij, Wc, Wn, We, (float*)d_out);
}

// round 10
// speedup vs baseline: 1.5555x; 1.0214x over previous
#include <cuda_runtime.h>
#include <cstdint>

// ---------------------------------------------------------------------------
// fused: out = relu(x@Wc^T + mean_k(x[nh])@Wn^T + mean_k(e)@We^T)
// mma.sync m16n8k8 tf32; M=64 rows/tile, N=128, K=320 = [x|mean x[nh]|mean e]
// 2 CTAs/SM (101KB SMEM each), 512 thr/CTA. ij int32. Streaming hints on e/ij/out.
// R9 (resubmit; prior run died to container infra failure, kernel re-audited):
//   (1) double-buffered W chunks (KCH=16) -> W LDG latency hidden, 1 bar/chunk
//   (2) ldmatrix.x4 fragment loads (tf32 rows = 16B b16-tiles) -> 12 LDS -> 3 LDSM
// ---------------------------------------------------------------------------

#define FULLMASK 0xFFFFFFFFu

static constexpr int NR     = 100000;
static constexpr int TM     = 64;                   // rows per tile
static constexpr int NTILES = (NR + TM - 1) / TM;   // 1563
static constexpr int AS     = 324;                  // A smem stride (floats)
static constexpr int WS     = 20;                   // W chunk stride (floats)
static constexpr int KCH    = 16;                   // K per W chunk
static constexpr int NCH    = 20;                   // 20 * 16 = 320
static constexpr int NTHR   = 512;
static constexpr unsigned A_BYTES = TM * AS * 4;        // 82944
static constexpr unsigned WBUF_B  = 128 * WS * 4;       // 10240 per buffer
static constexpr unsigned SMEM_DYN = A_BYTES + 2 * WBUF_B;  // 103424 B -> 2 CTAs/SM

static __device__ __forceinline__ uint32_t smem_u32(const void* p) {
    uint32_t a;
    asm("{ .reg .u64 t; cvta.to.shared.u64 t, %1; cvt.u32.u64 %0, t; }"
        : "=r"(a) : "l"(p));
    return a;
}

static __device__ __forceinline__ uint32_t f2tf(float f) {
    uint32_t r;
    asm("cvt.rna.tf32.f32 %0, %1;" : "=r"(r) : "f"(f));
    return r;
}

static __device__ __forceinline__ void mma8(float* c, const uint32_t* a,
                                            uint32_t b0, uint32_t b1) {
    asm volatile(
        "mma.sync.aligned.m16n8k8.row.col.f32.tf32.tf32.f32 "
        "{%0,%1,%2,%3}, {%4,%5,%6,%7}, {%8,%9}, {%0,%1,%2,%3};"
        : "+f"(c[0]), "+f"(c[1]), "+f"(c[2]), "+f"(c[3])
        : "r"(a[0]), "r"(a[1]), "r"(a[2]), "r"(a[3]), "r"(b0), "r"(b1));
}

#define LDSM_X4(r0, r1, r2, r3, addr)                                          \
    asm volatile("ldmatrix.sync.aligned.m8n8.x4.shared.b16 {%0,%1,%2,%3}, [%4];" \
                 : "=r"(r0), "=r"(r1), "=r"(r2), "=r"(r3) : "r"(addr))

__global__ void __launch_bounds__(NTHR, 2)
conv_block_fused(const float* __restrict__ x, const float* __restrict__ e,
                 const int* __restrict__ ij,
                 const float* __restrict__ Wc, const float* __restrict__ Wn,
                 const float* __restrict__ We, float* __restrict__ out)
{
    extern __shared__ uint32_t smem[];
    uint32_t* As = smem;                        // A tile, tf32 bits, [64][AS]
    uint32_t* Wb = smem + TM * AS;              // W buffers, 2 x [128][WS]

    const int tid  = threadIdx.x;
    const int wid  = tid >> 5;       // 0..15
    const int lane = tid & 31;
    const int gid  = lane >> 2;      // 0..7
    const int tq   = lane & 3;       // 0..3
    const int row0 = blockIdx.x * TM;

    // ---------------- build A tile: warp per row, lane per column ----------
    {
        const float inv = 1.0f / 16.0f;
        const int r0  = wid * 4;
        const int rgb = row0 + r0;

        // prefetch ij for all 4 rows of this warp (2 streamed LDGs)
        int nh01 = 0, nh23 = 0;
        {
            const int rowsel = lane >> 4;       // 0 or 1
            const int nidx   = lane & 15;
            const int ra = rgb + rowsel;
            const int rb = rgb + 2 + rowsel;
            if (ra < NR) nh01 = __ldcs(ij + ra * 32 + nidx * 2);
            if (rb < NR) nh23 = __ldcs(ij + rb * 32 + nidx * 2);
        }

        #pragma unroll 1
        for (int rr = 0; rr < 4; rr++) {
            const int r  = r0 + rr;
            const int rg = row0 + r;
            const bool valid = (rg < NR);

            const int nsrc = (rr < 2) ? nh01 : nh23;
            int rk[16];
            #pragma unroll
            for (int k = 0; k < 16; k++)
                rk[k] = __shfl_sync(FULLMASK, nsrc, (rr & 1) * 16 + k);

            float4 xv = make_float4(0.f, 0.f, 0.f, 0.f);
            float4 ac = make_float4(0.f, 0.f, 0.f, 0.f);
            if (valid) {
                xv = *(const float4*)(x + rg * 128 + lane * 4);
                #pragma unroll
                for (int k = 0; k < 16; k++) {
                    // default caching: keep x L2-resident
                    const float4 t = *(const float4*)(x + rk[k] * 128 + lane * 4);
                    ac.x += t.x; ac.y += t.y; ac.z += t.z; ac.w += t.w;
                }
            }
            ac.x *= inv; ac.y *= inv; ac.z *= inv; ac.w *= inv;

            uint32_t* a0 = As + r * AS + lane * 4;
            a0[0] = f2tf(xv.x); a0[1] = f2tf(xv.y); a0[2] = f2tf(xv.z); a0[3] = f2tf(xv.w);
            uint32_t* a1 = As + r * AS + 128 + lane * 4;
            a1[0] = f2tf(ac.x); a1[1] = f2tf(ac.y); a1[2] = f2tf(ac.z); a1[3] = f2tf(ac.w);

            float2 ea = make_float2(0.f, 0.f);
            if (valid) {
                // e is a read-once stream: evict-first
                const float2* ep = (const float2*)(e + rg * 1024 + lane * 2);
                #pragma unroll
                for (int k = 0; k < 16; k++) {
                    const float2 t = __ldcs(ep + k * 32);
                    ea.x += t.x; ea.y += t.y;
                }
            }
            ea.x *= inv; ea.y *= inv;
            uint32_t* a2 = As + r * AS + 256 + lane * 2;
            a2[0] = f2tf(ea.x); a2[1] = f2tf(ea.y);
        }
    }

    // ---------------- GEMM: mma.sync tf32, warp tile 16(M) x 32(N) --------
    const int m0 = (wid & 3) * 16;
    const int n0 = (wid >> 2) * 32;

    // per-lane ldmatrix row addresses (byte smem addresses)
    const uint32_t sb   = smem_u32(smem);
    const uint32_t Wsb  = sb + A_BYTES;
    const int t8 = lane >> 3;        // tile index 0..3
    const int w8 = lane & 7;         // row within tile
    // A tiles: t = {rows 0-7 klo, rows 8-15 klo, rows 0-7 khi, rows 8-15 khi}
    const uint32_t a_lane = sb +
        (((m0 + (t8 & 1) * 8 + w8) * AS) + (t8 >> 1) * 4) * 4;
    // B tiles set1: t = {j0 klo, j0 khi, j1 klo, j1 khi}
    const uint32_t b_lane1 = Wsb +
        (((n0 + (t8 >> 1) * 8 + w8) * WS) + (t8 & 1) * 4) * 4;
    const uint32_t b_lane2 = b_lane1 + 16 * WS * 4;   // j+2

    float acc[4][4];
    #pragma unroll
    for (int j = 0; j < 4; j++)
        #pragma unroll
        for (int q = 0; q < 4; q++) acc[j][q] = 0.f;

    // W gmem lane mapping: one float4 per thread per chunk
    const int nrow = tid >> 2;       // 0..127
    const int k4   = tid & 3;        // 0..3
    uint32_t* wdst_base = Wb + nrow * WS + k4 * 4;

    // preload chunk 0 (Wc, koff 0)
    {
        const float4 v = *(const float4*)(Wc + nrow * 128 + k4 * 4);
        uint32_t* d = wdst_base;     // buffer 0
        d[0] = f2tf(v.x); d[1] = f2tf(v.y); d[2] = f2tf(v.z); d[3] = f2tf(v.w);
    }
    __syncthreads();   // A tile + W chunk 0 ready

    #pragma unroll 1
    for (int c = 0; c < NCH; c++) {
        // issue next W chunk load early (latency hidden by compute)
        float4 wv;
        const int nc = c + 1;
        if (nc < NCH) {
            const float* src; int koff; int sk;
            if (nc < 8)       { src = Wc; koff = nc * 16;        sk = 128; }
            else if (nc < 16) { src = Wn; koff = (nc - 8) * 16;  sk = 128; }
            else              { src = We; koff = (nc - 16) * 16; sk = 64;  }
            wv = *(const float4*)(src + nrow * sk + koff + k4 * 4);
        }

        // compute 2 ksteps of this chunk
        const uint32_t abase = a_lane + (uint32_t)(c * KCH * 4);
        const uint32_t wbase = (uint32_t)((c & 1) * (int)WBUF_B);
        #pragma unroll
        for (int s = 0; s < 2; s++) {
            uint32_t a[4], b0, b1, b2, b3, b4, b5, b6, b7;
            LDSM_X4(a[0], a[1], a[2], a[3], abase + s * 32);
            LDSM_X4(b0, b1, b2, b3, b_lane1 + wbase + s * 32);
            LDSM_X4(b4, b5, b6, b7, b_lane2 + wbase + s * 32);
            mma8(acc[0], a, b0, b1);
            mma8(acc[1], a, b2, b3);
            mma8(acc[2], a, b4, b5);
            mma8(acc[3], a, b6, b7);
        }

        // store next chunk into the other buffer (its readers finished at bar c-1)
        if (nc < NCH) {
            uint32_t* d = wdst_base + (nc & 1) * (WBUF_B / 4);
            d[0] = f2tf(wv.x); d[1] = f2tf(wv.y); d[2] = f2tf(wv.z); d[3] = f2tf(wv.w);
        }
        __syncthreads();
    }

    // ---------------- epilogue: relu + store (write-once: streaming) ------
    {
        const int rg0 = row0 + m0 + gid;
        const int rg1 = rg0 + 8;
        #pragma unroll
        for (int j = 0; j < 4; j++) {
            const int col = n0 + j * 8 + tq * 2;
            if (rg0 < NR) {
                float2 v;
                v.x = fmaxf(acc[j][0], 0.f);
                v.y = fmaxf(acc[j][1], 0.f);
                __stcs((float2*)(out + rg0 * 128 + col), v);
            }
            if (rg1 < NR) {
                float2 v;
                v.x = fmaxf(acc[j][2], 0.f);
                v.y = fmaxf(acc[j][3], 0.f);
                __stcs((float2*)(out + rg1 * 128 + col), v);
            }
        }
    }
}

extern "C" void kernel_launch(void* const* d_in, const int* in_sizes, int n_in,
                              void* d_out, int out_size)
{
    (void)in_sizes; (void)n_in; (void)out_size;
    const float* x  = (const float*)d_in[0];
    const float* e  = (const float*)d_in[1];
    const int*   ij = (const int*)d_in[2];
    const float* Wc = (const float*)d_in[3];
    const float* Wn = (const float*)d_in[4];
    const float* We = (const float*)d_in[5];

    cudaFuncSetAttribute(conv_block_fused,
                         cudaFuncAttributeMaxDynamicSharedMemorySize, SMEM_DYN);
    conv_block_fused<<<NTILES, NTHR, SMEM_DYN>>>(x, e, ij, Wc, Wn, We, (float*)d_out);
}